// round 13
// baseline (speedup 1.0000x reference)
#include <cuda_runtime.h>
#include <math.h>

#define HH 208
#define WW 336
#define NA 3
#define NPIX (HH*WW)            // 69888 per image
#define NPI (NPIX*NA)           // 209664 anchors per image
#define NB 2
#define PRE 2000
#define POST 1000
#define PRE_PAD 2048
#define CAND_CAP 4096
#define BBOX_CLIP 4.135166556742356f

// ---- output layout offsets (floats) ----
#define OFF_CLS   0
#define OFF_BBOX  (NB*NPIX*3)                // 419328
#define OFF_ROIS  (OFF_BBOX + NB*NPIX*12)    // 2096640
#define OFF_RSC   (OFF_ROIS + NB*POST*4)     // 2104640

// ---- device scratch ----
__device__ float              g_scores[NB][NPI];
__device__ unsigned int       g_h16[NB][65536];     // zeroed at load; re-zeroed by compact_kernel
__device__ int                g_pivot[NB];
__device__ int                g_cnt[NB];
__device__ unsigned long long g_cand[NB][CAND_CAP];
__device__ float              g_pre_scores[NB][PRE_PAD];
__device__ float4             g_pre_boxes[NB][PRE_PAD];
__device__ unsigned long long g_mask[NB][PRE_PAD][32];

// ---- spacer kernels: ncu samples launch #4; keep head there ----
__global__ void spacer_kernel() {}

// ============================================================
// K1 v5: fused 1x1 convs + sigmoid + histogram + raw bbox store
// TILE=256, 1 pixel/thread, scalar acc (low regs -> 4 blocks/SM),
// block-wide transpose staging (L1-cheap), reg-prefetch of cc+1.
// ============================================================
#define HTILE  256
#define PITCHB 258              // 258 mod 32 = 2 -> conflict-free store & read

__global__ void __launch_bounds__(256, 4) head_kernel(
        const float* __restrict__ feats,
        const float* __restrict__ w_cls,
        const float* __restrict__ b_cls,
        const float* __restrict__ w_reg,
        const float* __restrict__ b_reg,
        float* __restrict__ out_cls,
        float* __restrict__ out_bbox) {
    __shared__ __align__(16) float wsm[4096];     // [ch 0..255][o 0..15], o=15 pad
    __shared__ float sf[16 * PITCHB];             // 16 channels x 256 pixels (+pad)

    int t = threadIdx.x;
    int p0 = blockIdx.x * HTILE;
    const float4* f4 = (const float4*)feats;

    // stage ALL weights once
#pragma unroll
    for (int i = t; i < 4096; i += 256) {
        int ch = i >> 4, o = i & 15;
        wsm[i] = (o < 3) ? w_cls[ch*3 + o] : (o < 15 ? w_reg[ch*12 + (o-3)] : 0.f);
    }

    float acc[15];
#pragma unroll
    for (int o = 0; o < 15; o++) acc[o] = 0.f;

    // prefetch cc = 0 (1024 float4 by 256 threads -> 4 each)
    int pl = t >> 2, c4 = t & 3;                  // thread's (pixel-base, channel-quad)
    float4 st[4];
#pragma unroll
    for (int u = 0; u < 4; u++)
        st[u] = f4[(size_t)(p0 + u*64 + pl)*64 + c4];
    __syncthreads();                              // weights staged

    for (int cc = 0; cc < 16; cc++) {
        // store staged chunk, transposed (conflict-free: PITCHB%32==2)
#pragma unroll
        for (int u = 0; u < 4; u++) {
            int px = u*64 + pl;
            sf[(c4*4+0)*PITCHB + px] = st[u].x;
            sf[(c4*4+1)*PITCHB + px] = st[u].y;
            sf[(c4*4+2)*PITCHB + px] = st[u].z;
            sf[(c4*4+3)*PITCHB + px] = st[u].w;
        }
        __syncthreads();
        // prefetch next chunk — overlapped with compute below
        if (cc < 15) {
#pragma unroll
            for (int u = 0; u < 4; u++)
                st[u] = f4[(size_t)(p0 + u*64 + pl)*64 + (cc+1)*4 + c4];
        }
        const float4* wq = ((const float4*)wsm) + cc*64;   // 16 rows x 4 float4
#pragma unroll
        for (int cl = 0; cl < 16; cl++) {
            float fv = sf[cl*PITCHB + t];
            float4 w0 = wq[cl*4+0], w1 = wq[cl*4+1], w2 = wq[cl*4+2], w3 = wq[cl*4+3];
            acc[0]  = fmaf(fv, w0.x, acc[0]);  acc[1]  = fmaf(fv, w0.y, acc[1]);
            acc[2]  = fmaf(fv, w0.z, acc[2]);  acc[3]  = fmaf(fv, w0.w, acc[3]);
            acc[4]  = fmaf(fv, w1.x, acc[4]);  acc[5]  = fmaf(fv, w1.y, acc[5]);
            acc[6]  = fmaf(fv, w1.z, acc[6]);  acc[7]  = fmaf(fv, w1.w, acc[7]);
            acc[8]  = fmaf(fv, w2.x, acc[8]);  acc[9]  = fmaf(fv, w2.y, acc[9]);
            acc[10] = fmaf(fv, w2.z, acc[10]); acc[11] = fmaf(fv, w2.w, acc[11]);
            acc[12] = fmaf(fv, w3.x, acc[12]); acc[13] = fmaf(fv, w3.y, acc[13]);
            acc[14] = fmaf(fv, w3.z, acc[14]);
        }
        __syncthreads();                          // WAR: compute done before next store
    }

    // ---- epilogue: this thread's pixel ----
    int p  = p0 + t;
    int b  = p / NPIX;
    int hw = p % NPIX;
#pragma unroll
    for (int a = 0; a < 3; a++) {
        float cls = acc[a] + b_cls[a];
        __stcs(&out_cls[((size_t)b*NPIX + hw)*3 + a], cls);
        float score = 1.f / (1.f + expf(-cls));
        int n = hw*3 + a;
        g_scores[b][n] = score;
        atomicAdd(&g_h16[b][__float_as_uint(score) >> 16], 1u);

        float dy = acc[3 + a*4 + 0] + b_reg[a*4 + 0];
        float dx = acc[3 + a*4 + 1] + b_reg[a*4 + 1];
        float dh = acc[3 + a*4 + 2] + b_reg[a*4 + 2];
        float dw = acc[3 + a*4 + 3] + b_reg[a*4 + 3];
        size_t bb = ((size_t)b*NPIX + hw)*12 + a*4;
        __stcs(&out_bbox[bb+0], dy); __stcs(&out_bbox[bb+1], dx);
        __stcs(&out_bbox[bb+2], dh); __stcs(&out_bbox[bb+3], dw);
    }
}

// ============================================================
// K2: pivot-bin search (shfl hierarchical suffix scan)
// ============================================================
__global__ void __launch_bounds__(1024, 1) scan_kernel() {
    __shared__ unsigned int wabove[32];
    int b = blockIdx.x, t = threadIdx.x;
    int lane = t & 31, warp = t >> 5;
    const uint4* hv4 = (const uint4*)g_h16[b];
    unsigned sum = 0;
#pragma unroll
    for (int i = 0; i < 16; i++) {
        uint4 v = hv4[t*16 + i];
        sum += v.x + v.y + v.z + v.w;
    }
    unsigned suf = sum;
#pragma unroll
    for (int off = 1; off < 32; off <<= 1) {
        unsigned n = __shfl_down_sync(0xffffffffu, suf, off);
        if (lane + off < 32) suf += n;
    }
    if (lane == 0) wabove[warp] = suf;
    __syncthreads();
    if (warp == 0) {
        unsigned ws = wabove[lane];
        unsigned wsuf = ws;
#pragma unroll
        for (int off = 1; off < 32; off <<= 1) {
            unsigned n = __shfl_down_sync(0xffffffffu, wsuf, off);
            if (lane + off < 32) wsuf += n;
        }
        wabove[lane] = wsuf - ws;
    }
    __syncthreads();
    unsigned sufT = suf + wabove[warp];
    unsigned above = sufT - sum;
    if (sufT >= (unsigned)PRE && above < (unsigned)PRE) {
        unsigned cum = above;
        int pivot = t*64;
        const unsigned* hb = g_h16[b] + t*64;
        for (int j = 63; j >= 0; j--) {
            cum += hb[j];
            if (cum >= (unsigned)PRE) { pivot = t*64 + j; break; }
        }
        g_pivot[b] = pivot;
        g_cnt[b] = 0;
    }
}

// ============================================================
// K3: grid-wide compaction (bin >= pivot) + histogram re-zero
// ============================================================
__global__ void compact_kernel() {
    int t = threadIdx.x;
    int zid = blockIdx.x * 256 + t;        // 512*256 == 2*65536 exactly
    g_h16[zid >> 16][zid & 65535] = 0;

    int stride = gridDim.x * blockDim.x;
    int gid = blockIdx.x * blockDim.x + t;
#pragma unroll
    for (int b = 0; b < NB; b++) {
        int P = g_pivot[b];
        for (int n = gid; n < NPI; n += stride) {
            unsigned key = __float_as_uint(g_scores[b][n]);
            if ((int)(key >> 16) >= P) {
                int slot = atomicAdd(&g_cnt[b], 1);
                if (slot < CAND_CAP)
                    g_cand[b][slot] =
                        ((unsigned long long)key << 32) | (unsigned)(~(unsigned)n);
            }
        }
    }
}

// ============================================================
// K4: 2-D rank-by-counting scatter + on-the-fly decode/clip
// ============================================================
__global__ void __launch_bounds__(1024, 1) rank_kernel(
        const float* __restrict__ out_bbox,
        const float* __restrict__ img_info) {
    __shared__ unsigned long long s[CAND_CAP];
    int blk = blockIdx.x;
    int b = blk >> 6, part = blk & 63;
    int t = threadIdx.x;
    int C = min(g_cnt[b], CAND_CAP);

    int cand = part*64 + (t >> 4);
    if (part*64 >= C) return;

    for (int i = t; i < C; i += 1024) s[i] = g_cand[b][i];
    __syncthreads();

    unsigned long long k = (cand < C) ? s[cand] : 0ull;
    int stripe = t & 15;
    int r = 0;
    for (int j = stripe; j < C; j += 16) r += (s[j] > k);
#pragma unroll
    for (int off = 8; off >= 1; off >>= 1)
        r += __shfl_down_sync(0xffffffffu, r, off, 16);

    if (stripe == 0 && cand < C && r < PRE_PAD) {
        unsigned nn = ~(unsigned)(k & 0xffffffffull);
        int hw = nn / 3, a = nn % 3;
        int h = hw / WW, w = hw % WW;
        const float4* d4 = (const float4*)(out_bbox + ((size_t)b*NPIX + hw)*12 + a*4);
        float4 d = *d4;                       // (dy, dx, dh, dw), bias included
        float dy = d.x, dx = d.y;
        float dh = fminf(fmaxf(d.z, -BBOX_CLIP), BBOX_CLIP);
        float dw = fminf(fmaxf(d.w, -BBOX_CLIP), BBOX_CLIP);
        const float axs[3] = {1.0f, 1.4f, 0.7f};
        const float ays[3] = {1.0f, 0.7f, 1.4f};
        float ah = 32.f * ays[a], aw = 32.f * axs[a];
        float yc = (h + 0.5f) * 4.f, xc = (w + 0.5f) * 4.f;
        float hmax = img_info[b*2 + 0], wmax = img_info[b*2 + 1];
        float cy = dy*ah + yc, cx = dx*aw + xc;
        float hh2 = expf(dh)*ah, ww2 = expf(dw)*aw;
        float y1 = fminf(fmaxf(cy - 0.5f*hh2, 0.f), hmax);
        float x1 = fminf(fmaxf(cx - 0.5f*ww2, 0.f), wmax);
        float y2 = fminf(fmaxf(cy + 0.5f*hh2, 0.f), hmax);
        float x2 = fminf(fmaxf(cx + 0.5f*ww2, 0.f), wmax);
        g_pre_boxes[b][r]  = make_float4(y1, x1, y2, x2);
        g_pre_scores[b][r] = __uint_as_float((unsigned)(k >> 32));
    }
}

// ============================================================
// K5: pairwise suppression mask — 512 threads (16 warps) per block
// ============================================================
__global__ void __launch_bounds__(512) mask_kernel() {
    __shared__ float4 jb[PRE_PAD];
    __shared__ float  ca[PRE_PAD];
    int blk = blockIdx.x;
    int b = blk >> 6;
    int r = blk & 63;
    int it = r >> 1;
    int half = r & 1;
    int t = threadIdx.x;

    for (int i = t; i < PRE_PAD; i += 512) {
        float4 bx = g_pre_boxes[b][i];
        jb[i] = bx;
        ca[i] = 0.41176470588f * (bx.z - bx.x) * (bx.w - bx.y);  // 0.7/1.7 * area
    }
    __syncthreads();

    int lane = t & 31;
    int i = it*64 + half*32 + lane;
    float4 bi = jb[i];
    float cai = ca[i] + 4.1176e-9f;
    int nwords = 32 - it;
    for (int wq = t >> 5; wq < nwords; wq += 16) {
        int w = it + wq;
        int j0 = w * 64;
        unsigned long long m = 0;
#pragma unroll
        for (int bit = 0; bit < 64; bit++) {
            float4 bj = jb[j0 + bit];
            float y1 = fmaxf(bi.x, bj.x), x1 = fmaxf(bi.y, bj.y);
            float y2 = fminf(bi.z, bj.z), x2 = fminf(bi.w, bj.w);
            float inter = fmaxf(y2 - y1, 0.f) * fmaxf(x2 - x1, 0.f);
            if (inter > cai + ca[j0 + bit]) m |= (1ull << bit);
        }
        g_mask[b][i][w] = m;
    }
}

// ============================================================
// K6: chunked bitmask scan (exact greedy NMS order) + output
// ============================================================
__global__ void __launch_bounds__(1024, 1) nms_scan(float* __restrict__ out_rois,
                                                    float* __restrict__ out_rscores) {
    __shared__ unsigned long long removed[32];
    __shared__ unsigned long long sIntra[64];
    __shared__ unsigned long long partial[32][33];
    __shared__ short kept[POST + 8];
    __shared__ int s_kc, s_k0, s_nk;

    int b = blockIdx.x, t = threadIdx.x;
    if (t < 32) removed[t] = 0ull;
    if (t == 0) s_kc = 0;

    for (int c = 0; c < 32; c++) {
        __syncthreads();
        if (s_kc >= POST) break;                       // uniform
        if (t < 64) sIntra[t] = g_mask[b][c*64 + t][c];
        __syncthreads();
        if (t == 0) {
            unsigned long long R = removed[c];
            int k = s_kc;
            s_k0 = k;
            int lim = min(64, PRE - c*64);
#pragma unroll
            for (int base = 0; base < 64; base += 8) {
                unsigned long long si[8];
#pragma unroll
                for (int u = 0; u < 8; u++) si[u] = sIntra[base + u];
#pragma unroll
                for (int u = 0; u < 8; u++) {
                    int bit = base + u;
                    int keep = (bit < lim) & (k < POST) & (int)(~(R >> bit) & 1ull);
                    kept[k] = (short)(c*64 + bit);
                    R |= keep ? si[u] : 0ull;
                    k += keep;
                }
            }
            s_kc = k;
            s_nk = k - s_k0;
        }
        __syncthreads();
        int w = t & 31, g = t >> 5;
        unsigned long long acc = 0ull;
        int nk = s_nk, k0 = s_k0;
        if (w > c) {
            for (int rr = g; rr < nk; rr += 32)
                acc |= g_mask[b][(int)kept[k0 + rr]][w];
        }
        partial[g][w] = acc;
        __syncthreads();
        if (t < 32 && t > c) {
            unsigned long long vv = removed[t];
#pragma unroll
            for (int g2 = 0; g2 < 32; g2++) vv |= partial[g2][t];
            removed[t] = vv;
        }
    }
    __syncthreads();

    int kc = s_kc;
    for (int i = t; i < POST; i += 1024) {
        float4 bo; float sc;
        if (i < kc) { int j = kept[i]; bo = g_pre_boxes[b][j]; sc = g_pre_scores[b][j]; }
        else        { bo = g_pre_boxes[b][0]; sc = -1.f; }
        size_t o = ((size_t)b*POST + i) * 4;
        out_rois[o+0] = bo.x; out_rois[o+1] = bo.y;
        out_rois[o+2] = bo.z; out_rois[o+3] = bo.w;
        out_rscores[(size_t)b*POST + i] = sc;
    }
}

// ============================================================
extern "C" void kernel_launch(void* const* d_in, const int* in_sizes, int n_in,
                              void* d_out, int out_size) {
    const float* feats    = (const float*)d_in[0];
    const float* img_info = (const float*)d_in[1];
    const float* w_cls    = (const float*)d_in[2];
    const float* b_cls    = (const float*)d_in[3];
    const float* w_reg    = (const float*)d_in[4];
    const float* b_reg    = (const float*)d_in[5];
    float* out = (float*)d_out;

    float* out_cls  = out + OFF_CLS;
    float* out_bbox = out + OFF_BBOX;
    float* out_rois = out + OFF_ROIS;
    float* out_rsc  = out + OFF_RSC;

    // spacers: keep head_kernel at launch #4 (the slot ncu samples)
    spacer_kernel<<<1, 32>>>();
    spacer_kernel<<<1, 32>>>();
    spacer_kernel<<<1, 32>>>();

    head_kernel<<<(NB*NPIX)/HTILE, 256>>>(feats, w_cls, b_cls, w_reg, b_reg,
                                          out_cls, out_bbox);
    scan_kernel<<<NB, 1024>>>();
    compact_kernel<<<512, 256>>>();
    rank_kernel<<<NB*64, 1024>>>(out_bbox, img_info);
    mask_kernel<<<NB*64, 512>>>();
    nms_scan<<<NB, 1024>>>(out_rois, out_rsc);
}

// round 14
// speedup vs baseline: 1.4728x; 1.4728x over previous
#include <cuda_runtime.h>
#include <math.h>

#define HH 208
#define WW 336
#define NA 3
#define NPIX (HH*WW)            // 69888 per image
#define NPI (NPIX*NA)           // 209664 anchors per image
#define NB 2
#define PRE 2000
#define POST 1000
#define PRE_PAD 2048
#define CAND_CAP 4096
#define BBOX_CLIP 4.135166556742356f

// ---- output layout offsets (floats) ----
#define OFF_CLS   0
#define OFF_BBOX  (NB*NPIX*3)                // 419328
#define OFF_ROIS  (OFF_BBOX + NB*NPIX*12)    // 2096640
#define OFF_RSC   (OFF_ROIS + NB*POST*4)     // 2104640

// ---- device scratch ----
__device__ float              g_scores[NB][NPI];
__device__ unsigned int       g_h16[NB][65536];     // zeroed at load; re-zeroed by compact_kernel
__device__ int                g_pivot[NB];
__device__ int                g_cnt[NB];
__device__ unsigned long long g_cand[NB][CAND_CAP];
__device__ float              g_pre_scores[NB][PRE_PAD];
__device__ float4             g_pre_boxes[NB][PRE_PAD];
__device__ unsigned long long g_mask[NB][PRE_PAD][32];

// ---- spacer kernels: ncu samples launch #4; keep head there ----
__global__ void spacer_kernel() {}

// ============================================================
// K1 v6: output-split head. Thread = (2 pixels) x (4 outputs).
// 4 threads/pixel -> 4x warps (~40/SM) at 1/4 the weight LDS
// wavefronts (all weight/feature reads are multi-lane-shared).
// Block = 256 thr covers 128 pixels; grid = 1092.
// ============================================================
#define HB 128
#define PF 130                  // pitch: q*4P ≡ 8 (mod 32) -> conflict-free staging

__global__ void __launch_bounds__(256, 5) head_kernel(
        const float* __restrict__ feats,
        const float* __restrict__ w_cls,
        const float* __restrict__ b_cls,
        const float* __restrict__ w_reg,
        const float* __restrict__ b_reg,
        float* __restrict__ out_cls,
        float* __restrict__ out_bbox) {
    __shared__ __align__(16) float wsm[4096];     // [ch 0..255][o 0..15], o=15 pad
    __shared__ float sf[16 * PF];                 // [16 ch][128 px] (+pad); reused for outputs

    int t = threadIdx.x;
    int p0 = blockIdx.x * HB;
    const float4* f4 = (const float4*)feats;

    // stage ALL weights once
#pragma unroll
    for (int i = t; i < 4096; i += 256) {
        int ch = i >> 4, o = i & 15;
        wsm[i] = (o < 3) ? w_cls[ch*3 + o] : (o < 15 ? w_reg[ch*12 + (o-3)] : 0.f);
    }

    int og  = t & 3;                    // output quad 0..3
    int lpx = ((t >> 5) << 4) + (((t >> 2) & 7) << 1);  // local pixel-pair start

    float acc[8];                       // [k 0..3]=px0 outs, [4+k]=px1 outs
#pragma unroll
    for (int k = 0; k < 8; k++) acc[k] = 0.f;

    for (int cc = 0; cc < 16; cc++) {
        __syncthreads();                // weights staged / previous compute done
#pragma unroll
        for (int rep = 0; rep < 2; rep++) {
            int j  = t + rep*256;       // 0..511
            int px = j >> 2, q = j & 3;
            float4 v = f4[(size_t)(p0 + px)*64 + cc*4 + q];
            sf[(q*4+0)*PF + px] = v.x;
            sf[(q*4+1)*PF + px] = v.y;
            sf[(q*4+2)*PF + px] = v.z;
            sf[(q*4+3)*PF + px] = v.w;
        }
        __syncthreads();
        const float4* wq = ((const float4*)wsm) + cc*64;
#pragma unroll
        for (int cl = 0; cl < 16; cl++) {
            float2 fv = *(const float2*)&sf[cl*PF + lpx];
            float4 wv = wq[cl*4 + og];
            acc[0] = fmaf(fv.x, wv.x, acc[0]);
            acc[1] = fmaf(fv.x, wv.y, acc[1]);
            acc[2] = fmaf(fv.x, wv.z, acc[2]);
            acc[3] = fmaf(fv.x, wv.w, acc[3]);
            acc[4] = fmaf(fv.y, wv.x, acc[4]);
            acc[5] = fmaf(fv.y, wv.y, acc[5]);
            acc[6] = fmaf(fv.y, wv.z, acc[6]);
            acc[7] = fmaf(fv.y, wv.w, acc[7]);
        }
    }

    // redistribute outputs through smem: sf becomes [16 out][128 px]
    __syncthreads();
#pragma unroll
    for (int k = 0; k < 4; k++) {
        sf[(og*4+k)*PF + lpx]     = acc[k];
        sf[(og*4+k)*PF + lpx + 1] = acc[4+k];
    }
    __syncthreads();

    if (t < HB) {
        int p  = p0 + t;
        int b  = p / NPIX;
        int hw = p % NPIX;
        float f[15];
#pragma unroll
        for (int o = 0; o < 15; o++) f[o] = sf[o*PF + t];
#pragma unroll
        for (int a = 0; a < 3; a++) {
            float cls = f[a] + b_cls[a];
            __stcs(&out_cls[((size_t)b*NPIX + hw)*3 + a], cls);
            float score = 1.f / (1.f + expf(-cls));
            int n = hw*3 + a;
            g_scores[b][n] = score;
            atomicAdd(&g_h16[b][__float_as_uint(score) >> 16], 1u);

            float dy = f[3 + a*4 + 0] + b_reg[a*4 + 0];
            float dx = f[3 + a*4 + 1] + b_reg[a*4 + 1];
            float dh = f[3 + a*4 + 2] + b_reg[a*4 + 2];
            float dw = f[3 + a*4 + 3] + b_reg[a*4 + 3];
            size_t bb = ((size_t)b*NPIX + hw)*12 + a*4;
            __stcs(&out_bbox[bb+0], dy); __stcs(&out_bbox[bb+1], dx);
            __stcs(&out_bbox[bb+2], dh); __stcs(&out_bbox[bb+3], dw);
        }
    }
}

// ============================================================
// K2: pivot-bin search (shfl hierarchical suffix scan)
// ============================================================
__global__ void __launch_bounds__(1024, 1) scan_kernel() {
    __shared__ unsigned int wabove[32];
    int b = blockIdx.x, t = threadIdx.x;
    int lane = t & 31, warp = t >> 5;
    const uint4* hv4 = (const uint4*)g_h16[b];
    unsigned sum = 0;
#pragma unroll
    for (int i = 0; i < 16; i++) {
        uint4 v = hv4[t*16 + i];
        sum += v.x + v.y + v.z + v.w;
    }
    unsigned suf = sum;
#pragma unroll
    for (int off = 1; off < 32; off <<= 1) {
        unsigned n = __shfl_down_sync(0xffffffffu, suf, off);
        if (lane + off < 32) suf += n;
    }
    if (lane == 0) wabove[warp] = suf;
    __syncthreads();
    if (warp == 0) {
        unsigned ws = wabove[lane];
        unsigned wsuf = ws;
#pragma unroll
        for (int off = 1; off < 32; off <<= 1) {
            unsigned n = __shfl_down_sync(0xffffffffu, wsuf, off);
            if (lane + off < 32) wsuf += n;
        }
        wabove[lane] = wsuf - ws;
    }
    __syncthreads();
    unsigned sufT = suf + wabove[warp];
    unsigned above = sufT - sum;
    if (sufT >= (unsigned)PRE && above < (unsigned)PRE) {
        unsigned cum = above;
        int pivot = t*64;
        const unsigned* hb = g_h16[b] + t*64;
        for (int j = 63; j >= 0; j--) {
            cum += hb[j];
            if (cum >= (unsigned)PRE) { pivot = t*64 + j; break; }
        }
        g_pivot[b] = pivot;
        g_cnt[b] = 0;
    }
}

// ============================================================
// K3: grid-wide compaction (bin >= pivot) + histogram re-zero
// ============================================================
__global__ void compact_kernel() {
    int t = threadIdx.x;
    int zid = blockIdx.x * 256 + t;        // 512*256 == 2*65536 exactly
    g_h16[zid >> 16][zid & 65535] = 0;

    int stride = gridDim.x * blockDim.x;
    int gid = blockIdx.x * blockDim.x + t;
#pragma unroll
    for (int b = 0; b < NB; b++) {
        int P = g_pivot[b];
        for (int n = gid; n < NPI; n += stride) {
            unsigned key = __float_as_uint(g_scores[b][n]);
            if ((int)(key >> 16) >= P) {
                int slot = atomicAdd(&g_cnt[b], 1);
                if (slot < CAND_CAP)
                    g_cand[b][slot] =
                        ((unsigned long long)key << 32) | (unsigned)(~(unsigned)n);
            }
        }
    }
}

// ============================================================
// K4: 2-D rank-by-counting scatter + on-the-fly decode/clip
// ============================================================
__global__ void __launch_bounds__(1024, 1) rank_kernel(
        const float* __restrict__ out_bbox,
        const float* __restrict__ img_info) {
    __shared__ unsigned long long s[CAND_CAP];
    int blk = blockIdx.x;
    int b = blk >> 6, part = blk & 63;
    int t = threadIdx.x;
    int C = min(g_cnt[b], CAND_CAP);

    int cand = part*64 + (t >> 4);
    if (part*64 >= C) return;

    for (int i = t; i < C; i += 1024) s[i] = g_cand[b][i];
    __syncthreads();

    unsigned long long k = (cand < C) ? s[cand] : 0ull;
    int stripe = t & 15;
    int r = 0;
    for (int j = stripe; j < C; j += 16) r += (s[j] > k);
#pragma unroll
    for (int off = 8; off >= 1; off >>= 1)
        r += __shfl_down_sync(0xffffffffu, r, off, 16);

    if (stripe == 0 && cand < C && r < PRE_PAD) {
        unsigned nn = ~(unsigned)(k & 0xffffffffull);
        int hw = nn / 3, a = nn % 3;
        int h = hw / WW, w = hw % WW;
        const float4* d4 = (const float4*)(out_bbox + ((size_t)b*NPIX + hw)*12 + a*4);
        float4 d = *d4;                       // (dy, dx, dh, dw), bias included
        float dy = d.x, dx = d.y;
        float dh = fminf(fmaxf(d.z, -BBOX_CLIP), BBOX_CLIP);
        float dw = fminf(fmaxf(d.w, -BBOX_CLIP), BBOX_CLIP);
        const float axs[3] = {1.0f, 1.4f, 0.7f};
        const float ays[3] = {1.0f, 0.7f, 1.4f};
        float ah = 32.f * ays[a], aw = 32.f * axs[a];
        float yc = (h + 0.5f) * 4.f, xc = (w + 0.5f) * 4.f;
        float hmax = img_info[b*2 + 0], wmax = img_info[b*2 + 1];
        float cy = dy*ah + yc, cx = dx*aw + xc;
        float hh2 = expf(dh)*ah, ww2 = expf(dw)*aw;
        float y1 = fminf(fmaxf(cy - 0.5f*hh2, 0.f), hmax);
        float x1 = fminf(fmaxf(cx - 0.5f*ww2, 0.f), wmax);
        float y2 = fminf(fmaxf(cy + 0.5f*hh2, 0.f), hmax);
        float x2 = fminf(fmaxf(cx + 0.5f*ww2, 0.f), wmax);
        g_pre_boxes[b][r]  = make_float4(y1, x1, y2, x2);
        g_pre_scores[b][r] = __uint_as_float((unsigned)(k >> 32));
    }
}

// ============================================================
// K5: pairwise suppression mask — 512 threads (16 warps) per block
// ============================================================
__global__ void __launch_bounds__(512) mask_kernel() {
    __shared__ float4 jb[PRE_PAD];
    __shared__ float  ca[PRE_PAD];
    int blk = blockIdx.x;
    int b = blk >> 6;
    int r = blk & 63;
    int it = r >> 1;
    int half = r & 1;
    int t = threadIdx.x;

    for (int i = t; i < PRE_PAD; i += 512) {
        float4 bx = g_pre_boxes[b][i];
        jb[i] = bx;
        ca[i] = 0.41176470588f * (bx.z - bx.x) * (bx.w - bx.y);  // 0.7/1.7 * area
    }
    __syncthreads();

    int lane = t & 31;
    int i = it*64 + half*32 + lane;
    float4 bi = jb[i];
    float cai = ca[i] + 4.1176e-9f;
    int nwords = 32 - it;
    for (int wq = t >> 5; wq < nwords; wq += 16) {
        int w = it + wq;
        int j0 = w * 64;
        unsigned long long m = 0;
#pragma unroll
        for (int bit = 0; bit < 64; bit++) {
            float4 bj = jb[j0 + bit];
            float y1 = fmaxf(bi.x, bj.x), x1 = fmaxf(bi.y, bj.y);
            float y2 = fminf(bi.z, bj.z), x2 = fminf(bi.w, bj.w);
            float inter = fmaxf(y2 - y1, 0.f) * fmaxf(x2 - x1, 0.f);
            if (inter > cai + ca[j0 + bit]) m |= (1ull << bit);
        }
        g_mask[b][i][w] = m;
    }
}

// ============================================================
// K6: chunked bitmask scan (exact greedy NMS order) + output
// ============================================================
__global__ void __launch_bounds__(1024, 1) nms_scan(float* __restrict__ out_rois,
                                                    float* __restrict__ out_rscores) {
    __shared__ unsigned long long removed[32];
    __shared__ unsigned long long sIntra[64];
    __shared__ unsigned long long partial[32][33];
    __shared__ short kept[POST + 8];
    __shared__ int s_kc, s_k0, s_nk;

    int b = blockIdx.x, t = threadIdx.x;
    if (t < 32) removed[t] = 0ull;
    if (t == 0) s_kc = 0;

    for (int c = 0; c < 32; c++) {
        __syncthreads();
        if (s_kc >= POST) break;                       // uniform
        if (t < 64) sIntra[t] = g_mask[b][c*64 + t][c];
        __syncthreads();
        if (t == 0) {
            unsigned long long R = removed[c];
            int k = s_kc;
            s_k0 = k;
            int lim = min(64, PRE - c*64);
#pragma unroll
            for (int base = 0; base < 64; base += 8) {
                unsigned long long si[8];
#pragma unroll
                for (int u = 0; u < 8; u++) si[u] = sIntra[base + u];
#pragma unroll
                for (int u = 0; u < 8; u++) {
                    int bit = base + u;
                    int keep = (bit < lim) & (k < POST) & (int)(~(R >> bit) & 1ull);
                    kept[k] = (short)(c*64 + bit);
                    R |= keep ? si[u] : 0ull;
                    k += keep;
                }
            }
            s_kc = k;
            s_nk = k - s_k0;
        }
        __syncthreads();
        int w = t & 31, g = t >> 5;
        unsigned long long acc = 0ull;
        int nk = s_nk, k0 = s_k0;
        if (w > c) {
            for (int rr = g; rr < nk; rr += 32)
                acc |= g_mask[b][(int)kept[k0 + rr]][w];
        }
        partial[g][w] = acc;
        __syncthreads();
        if (t < 32 && t > c) {
            unsigned long long vv = removed[t];
#pragma unroll
            for (int g2 = 0; g2 < 32; g2++) vv |= partial[g2][t];
            removed[t] = vv;
        }
    }
    __syncthreads();

    int kc = s_kc;
    for (int i = t; i < POST; i += 1024) {
        float4 bo; float sc;
        if (i < kc) { int j = kept[i]; bo = g_pre_boxes[b][j]; sc = g_pre_scores[b][j]; }
        else        { bo = g_pre_boxes[b][0]; sc = -1.f; }
        size_t o = ((size_t)b*POST + i) * 4;
        out_rois[o+0] = bo.x; out_rois[o+1] = bo.y;
        out_rois[o+2] = bo.z; out_rois[o+3] = bo.w;
        out_rscores[(size_t)b*POST + i] = sc;
    }
}

// ============================================================
extern "C" void kernel_launch(void* const* d_in, const int* in_sizes, int n_in,
                              void* d_out, int out_size) {
    const float* feats    = (const float*)d_in[0];
    const float* img_info = (const float*)d_in[1];
    const float* w_cls    = (const float*)d_in[2];
    const float* b_cls    = (const float*)d_in[3];
    const float* w_reg    = (const float*)d_in[4];
    const float* b_reg    = (const float*)d_in[5];
    float* out = (float*)d_out;

    float* out_cls  = out + OFF_CLS;
    float* out_bbox = out + OFF_BBOX;
    float* out_rois = out + OFF_ROIS;
    float* out_rsc  = out + OFF_RSC;

    // spacers: keep head_kernel at launch #4 (the slot ncu samples)
    spacer_kernel<<<1, 32>>>();
    spacer_kernel<<<1, 32>>>();
    spacer_kernel<<<1, 32>>>();

    head_kernel<<<(NB*NPIX)/HB, 256>>>(feats, w_cls, b_cls, w_reg, b_reg,
                                       out_cls, out_bbox);
    scan_kernel<<<NB, 1024>>>();
    compact_kernel<<<512, 256>>>();
    rank_kernel<<<NB*64, 1024>>>(out_bbox, img_info);
    mask_kernel<<<NB*64, 512>>>();
    nms_scan<<<NB, 1024>>>(out_rois, out_rsc);
}